// round 5
// baseline (speedup 1.0000x reference)
#include <cuda_runtime.h>
#include <cuda_bf16.h>
#include <math.h>
#include <stdint.h>

#define S_LEN 2048
#define HID   2048
#define NH    32
#define NKV   8
#define HD    64
#define KVW   1024          // combined [K|V] width

// ---------------- scratch (no allocs allowed) ----------------
__device__ float g_q [S_LEN * HID];
__device__ float g_kv[S_LEN * KVW];   // cols 0..511 = K, 512..1023 = V

__device__ __nv_bfloat16 g_Xhi [S_LEN * HID], g_Xlo [S_LEN * HID];
__device__ __nv_bfloat16 g_Wqhi[HID * HID],   g_Wqlo[HID * HID];
__device__ __nv_bfloat16 g_Wkvhi[HID * KVW],  g_Wkvlo[HID * KVW];
__device__ __nv_bfloat16 g_Wohi[HID * HID],   g_Wolo[HID * HID];
__device__ __nv_bfloat16 g_Ahi [S_LEN * HID], g_Alo [S_LEN * HID];

// attention operands (bf16 hi/lo after RoPE)
__device__ __nv_bfloat16 g_qh[S_LEN * HID], g_ql[S_LEN * HID];
__device__ __nv_bfloat16 g_kh[S_LEN * 512], g_kl[S_LEN * 512];
__device__ __nv_bfloat16 g_vh[S_LEN * 512], g_vl[S_LEN * 512];

// ---------------- helpers ----------------
__device__ __forceinline__ uint32_t sptr(const void* p) {
    return (uint32_t)__cvta_generic_to_shared(p);
}
__device__ __forceinline__ void cp16(uint32_t dst, const void* src) {
    asm volatile("cp.async.cg.shared.global [%0], [%1], 16;\n" :: "r"(dst), "l"(src));
}
__device__ __forceinline__ void ldsm_x4(uint32_t* r, uint32_t addr) {
    asm volatile("ldmatrix.sync.aligned.m8n8.x4.shared.b16 {%0,%1,%2,%3}, [%4];\n"
        : "=r"(r[0]), "=r"(r[1]), "=r"(r[2]), "=r"(r[3]) : "r"(addr));
}
__device__ __forceinline__ void ldsm_x4_t(uint32_t* r, uint32_t addr) {
    asm volatile("ldmatrix.sync.aligned.m8n8.x4.trans.shared.b16 {%0,%1,%2,%3}, [%4];\n"
        : "=r"(r[0]), "=r"(r[1]), "=r"(r[2]), "=r"(r[3]) : "r"(addr));
}
__device__ __forceinline__ void mma16816(float* c, const uint32_t* a, const uint32_t* b) {
    asm volatile(
        "mma.sync.aligned.m16n8k16.row.col.f32.bf16.bf16.f32 "
        "{%0,%1,%2,%3}, {%4,%5,%6,%7}, {%8,%9}, {%0,%1,%2,%3};\n"
        : "+f"(c[0]), "+f"(c[1]), "+f"(c[2]), "+f"(c[3])
        : "r"(a[0]), "r"(a[1]), "r"(a[2]), "r"(a[3]), "r"(b[0]), "r"(b[1]));
}
__device__ __forceinline__ uint32_t packbf2(float x, float y) {
    __nv_bfloat162 h = __floats2bfloat162_rn(x, y);
    return *(uint32_t*)&h;
}

// ---------------- splits ----------------
__global__ void split_k(const float* __restrict__ in,
                        __nv_bfloat16* __restrict__ hi,
                        __nv_bfloat16* __restrict__ lo, int n)
{
    int i = blockIdx.x * 256 + threadIdx.x;
    if (i >= n) return;
    float x = in[i];
    __nv_bfloat16 h = __float2bfloat16(x);
    hi[i] = h;
    lo[i] = __float2bfloat16(x - __bfloat162float(h));
}

__global__ void split_pack_k(const float* __restrict__ in,
                             __nv_bfloat16* __restrict__ hi,
                             __nv_bfloat16* __restrict__ lo,
                             int rows, int cols, int ostride, int ooff)
{
    int i = blockIdx.x * 256 + threadIdx.x;
    if (i >= rows * cols) return;
    int r = i / cols, c = i % cols;
    float x = in[i];
    __nv_bfloat16 h = __float2bfloat16(x);
    int o = r * ostride + ooff + c;
    hi[o] = h;
    lo[o] = __float2bfloat16(x - __bfloat162float(h));
}

// ---------------- tensor-core GEMM: 128x256 CTA, 64x64 warp, 3-stage ----------------
#define BM 128
#define BN 256
#define BK 32
#define ASTRIDE 40                      // elems; 80B rows
#define BSTRIDE 264                     // elems; 528B rows (256+8)
#define A_T (BM * ASTRIDE)              // 5120 elems
#define B_T (BK * BSTRIDE)              // 8448 elems
#define STAGE_ELEMS (2 * A_T + 2 * B_T) // 27136 elems
#define NSTAGE 3
#define GEMM_SMEM_BYTES (NSTAGE * STAGE_ELEMS * 2)   // 162816

__device__ __forceinline__ void load_tile(
    __nv_bfloat16* sm,
    const __nv_bfloat16* __restrict__ Ah, const __nv_bfloat16* __restrict__ Al,
    const __nv_bfloat16* __restrict__ Bh, const __nv_bfloat16* __restrict__ Bl,
    int K, int N, int m0, int n0, int k0, int t)
{
    // A tile: 128 rows x 32 cols = 512 16B chunks (hi and lo)
    #pragma unroll
    for (int c = t; c < 512; c += 256) {
        int row = c >> 2, col = (c & 3) * 8;
        size_t g = (size_t)(m0 + row) * K + k0 + col;
        uint32_t s = (uint32_t)(row * ASTRIDE + col);
        cp16(sptr(sm + s),       Ah + g);
        cp16(sptr(sm + A_T + s), Al + g);
    }
    // B tile: 32 rows x 256 cols = 1024 16B chunks (hi and lo)
    #pragma unroll
    for (int c = t; c < 1024; c += 256) {
        int row = c >> 5, col = (c & 31) * 8;
        size_t g = (size_t)(k0 + row) * N + n0 + col;
        uint32_t s = (uint32_t)(row * BSTRIDE + col);
        cp16(sptr(sm + 2 * A_T + s),       Bh + g);
        cp16(sptr(sm + 2 * A_T + B_T + s), Bl + g);
    }
}

__global__ __launch_bounds__(256, 1) void mma_gemm(
    const __nv_bfloat16* __restrict__ Ah, const __nv_bfloat16* __restrict__ Al,
    const __nv_bfloat16* __restrict__ Bh, const __nv_bfloat16* __restrict__ Bl,
    float* __restrict__ C, int M, int N, int K)
{
    extern __shared__ __nv_bfloat16 sm[];
    const int t = threadIdx.x, lane = t & 31, w = t >> 5;
    const int wm = w >> 2, wn = w & 3;            // warp tile 64(M) x 64(N)
    const int m0 = blockIdx.y * BM, n0 = blockIdx.x * BN;

    float acc[4][8][4];
    #pragma unroll
    for (int i = 0; i < 4; i++)
        #pragma unroll
        for (int j = 0; j < 8; j++)
            #pragma unroll
            for (int r = 0; r < 4; r++) acc[i][j][r] = 0.f;

    const int g8 = lane >> 3;
    const int l8 = lane & 7;

    // prologue: stages 0,1
    load_tile(sm, Ah, Al, Bh, Bl, K, N, m0, n0, 0, t);
    asm volatile("cp.async.commit_group;\n");
    load_tile(sm + STAGE_ELEMS, Ah, Al, Bh, Bl, K, N, m0, n0, BK, t);
    asm volatile("cp.async.commit_group;\n");

    const int nk = K / BK;
    int sidx = 0;
    for (int kt = 0; kt < nk; kt++) {
        if (kt == nk - 1) asm volatile("cp.async.wait_group 0;\n");
        else              asm volatile("cp.async.wait_group 1;\n");
        __syncthreads();
        __nv_bfloat16* buf = sm + sidx * STAGE_ELEMS;

        #pragma unroll
        for (int ks = 0; ks < 2; ks++) {
            uint32_t ah[4][4], al[4][4], bh[8][2], bl[8][2];
            #pragma unroll
            for (int i = 0; i < 4; i++) {
                int row = wm * 64 + i * 16 + (g8 & 1) * 8 + l8;
                int col = ks * 16 + (g8 >> 1) * 8;
                ldsm_x4(ah[i], sptr(buf + row * ASTRIDE + col));
                ldsm_x4(al[i], sptr(buf + A_T + row * ASTRIDE + col));
            }
            #pragma unroll
            for (int jj = 0; jj < 4; jj++) {
                int krow = ks * 16 + (g8 & 1) * 8 + l8;
                int ncol = wn * 64 + jj * 16 + (g8 >> 1) * 8;
                uint32_t r4[4];
                ldsm_x4_t(r4, sptr(buf + 2 * A_T + krow * BSTRIDE + ncol));
                bh[2 * jj][0] = r4[0]; bh[2 * jj][1] = r4[1];
                bh[2 * jj + 1][0] = r4[2]; bh[2 * jj + 1][1] = r4[3];
                ldsm_x4_t(r4, sptr(buf + 2 * A_T + B_T + krow * BSTRIDE + ncol));
                bl[2 * jj][0] = r4[0]; bl[2 * jj][1] = r4[1];
                bl[2 * jj + 1][0] = r4[2]; bl[2 * jj + 1][1] = r4[3];
            }
            #pragma unroll
            for (int i = 0; i < 4; i++)
                #pragma unroll
                for (int j = 0; j < 8; j++) {
                    mma16816(acc[i][j], ah[i], bh[j]);
                    mma16816(acc[i][j], ah[i], bl[j]);
                    mma16816(acc[i][j], al[i], bh[j]);
                }
        }

        if (kt + 2 < nk) {   // safe: buffer (kt+2)%3 was last read in iter kt-1
            load_tile(sm + ((sidx + 2) % NSTAGE) * STAGE_ELEMS, Ah, Al, Bh, Bl,
                      K, N, m0, n0, (kt + 2) * BK, t);
            asm volatile("cp.async.commit_group;\n");
        }
        sidx = (sidx + 1) % NSTAGE;
    }

    #pragma unroll
    for (int i = 0; i < 4; i++)
        #pragma unroll
        for (int j = 0; j < 8; j++) {
            int row = m0 + wm * 64 + i * 16 + (lane >> 2);
            int col = n0 + wn * 64 + j * 8 + (lane & 3) * 2;
            *(float2*)&C[(size_t)row * N + col] =
                make_float2(acc[i][j][0], acc[i][j][1]);
            *(float2*)&C[(size_t)(row + 8) * N + col] =
                make_float2(acc[i][j][2], acc[i][j][3]);
        }
}

// ---------------- fused RoPE + bf16 hi/lo split ----------------
__global__ void rope_split_k(const float* __restrict__ q,
                             const float* __restrict__ kv,
                             const int* __restrict__ pos_ids,
                             __nv_bfloat16* __restrict__ qh, __nv_bfloat16* __restrict__ ql,
                             __nv_bfloat16* __restrict__ kh, __nv_bfloat16* __restrict__ kl,
                             __nv_bfloat16* __restrict__ vh, __nv_bfloat16* __restrict__ vl)
{
    int idx = blockIdx.x * blockDim.x + threadIdx.x;
    const int total = S_LEN * 48 * 32;
    if (idx >= total) return;

    int d    = idx & 31;
    int rest = idx >> 5;
    int hh   = rest % 48;
    int s    = rest / 48;

    if (hh < 40) {
        float pos = (float)pos_ids[s];
        float inv = __powf(10000.0f, -(float)d * (1.0f / 32.0f));
        float ang = pos * inv;
        float c, sn;
        __sincosf(ang, &sn, &c);
        if (hh < 32) {
            const float* p = q + (size_t)s * HID + hh * HD;
            float x1 = p[d], x2 = p[d + 32];
            size_t o1 = (size_t)s * HID + hh * HD + d, o2 = o1 + 32;
            float y1 = (x1 * c - x2 * sn) * 0.125f;
            float y2 = (x2 * c + x1 * sn) * 0.125f;
            __nv_bfloat16 h1 = __float2bfloat16(y1), h2 = __float2bfloat16(y2);
            qh[o1] = h1; ql[o1] = __float2bfloat16(y1 - __bfloat162float(h1));
            qh[o2] = h2; ql[o2] = __float2bfloat16(y2 - __bfloat162float(h2));
        } else {
            const float* p = kv + (size_t)s * KVW + (hh - 32) * HD;
            float x1 = p[d], x2 = p[d + 32];
            size_t o1 = (size_t)s * 512 + (hh - 32) * HD + d, o2 = o1 + 32;
            float y1 = x1 * c - x2 * sn;
            float y2 = x2 * c + x1 * sn;
            __nv_bfloat16 h1 = __float2bfloat16(y1), h2 = __float2bfloat16(y2);
            kh[o1] = h1; kl[o1] = __float2bfloat16(y1 - __bfloat162float(h1));
            kh[o2] = h2; kl[o2] = __float2bfloat16(y2 - __bfloat162float(h2));
        }
    } else {
        const float* p = kv + (size_t)s * KVW + 512 + (hh - 40) * HD;
        float x1 = p[d], x2 = p[d + 32];
        size_t o1 = (size_t)s * 512 + (hh - 40) * HD + d, o2 = o1 + 32;
        __nv_bfloat16 h1 = __float2bfloat16(x1), h2 = __float2bfloat16(x2);
        vh[o1] = h1; vl[o1] = __float2bfloat16(x1 - __bfloat162float(h1));
        vh[o2] = h2; vl[o2] = __float2bfloat16(x2 - __bfloat162float(h2));
    }
}

// ---------------- tensor-core flash attention (causal) ----------------
#define QHI_OFF 0
#define QLO_OFF (128 * 144)
#define BUF_OFF (2 * 128 * 144)
#define KVBUF   (4 * 64 * 144)
#define ATTN_SMEM (BUF_OFF + 2 * KVBUF)

__device__ __forceinline__ void attn_load_kv(
    uint32_t bufb,
    const __nv_bfloat16* __restrict__ kh, const __nv_bfloat16* __restrict__ kl,
    const __nv_bfloat16* __restrict__ vh, const __nv_bfloat16* __restrict__ vl,
    int k0, int kvh, int t)
{
    #pragma unroll
    for (int i = 0; i < 2; i++) {
        int idx = i * 256 + t;
        int row = idx >> 3, cc = idx & 7;
        uint32_t off = (uint32_t)(row * 144 + cc * 16);
        size_t g = (size_t)(k0 + row) * 512 + kvh * HD + cc * 8;
        cp16(bufb + off,         kh + g);
        cp16(bufb + 9216 + off,  kl + g);
        cp16(bufb + 18432 + off, vh + g);
        cp16(bufb + 27648 + off, vl + g);
    }
}

__global__ __launch_bounds__(256) void attn_tc(
    const __nv_bfloat16* __restrict__ qh, const __nv_bfloat16* __restrict__ ql,
    const __nv_bfloat16* __restrict__ kh, const __nv_bfloat16* __restrict__ kl,
    const __nv_bfloat16* __restrict__ vh, const __nv_bfloat16* __restrict__ vl,
    __nv_bfloat16* __restrict__ Oh, __nv_bfloat16* __restrict__ Ol)
{
    extern __shared__ __align__(1024) char asmem[];
    const uint32_t sb = sptr(asmem);
    const int qt  = 15 - blockIdx.x;
    const int h   = blockIdx.y;
    const int kvh = h >> 2;
    const int t = threadIdx.x, w = t >> 5, lane = t & 31;
    const int g8 = lane >> 3, l8 = lane & 7, tig = lane & 3, g = lane >> 2;
    const int q0 = qt * 128;

    #pragma unroll
    for (int i = 0; i < 4; i++) {
        int idx = i * 256 + t;
        int row = idx >> 3, cc = idx & 7;
        uint32_t off = (uint32_t)(row * 144 + cc * 16);
        size_t gg = (size_t)(q0 + row) * HID + h * HD + cc * 8;
        cp16(sb + QHI_OFF + off, qh + gg);
        cp16(sb + QLO_OFF + off, ql + gg);
    }
    attn_load_kv(sb + BUF_OFF, kh, kl, vh, vl, 0, kvh, t);
    asm volatile("cp.async.commit_group;\n");
    asm volatile("cp.async.wait_group 0;\n");
    __syncthreads();

    uint32_t qah[4][4], qal[4][4];
    #pragma unroll
    for (int kc = 0; kc < 4; kc++) {
        uint32_t off = (uint32_t)((w * 16 + (g8 & 1) * 8 + l8) * 144 +
                                  (kc * 16 + (g8 >> 1) * 8) * 2);
        ldsm_x4(qah[kc], sb + QHI_OFF + off);
        ldsm_x4(qal[kc], sb + QLO_OFF + off);
    }

    float oacc[8][4];
    #pragma unroll
    for (int j = 0; j < 8; j++)
        #pragma unroll
        for (int r = 0; r < 4; r++) oacc[j][r] = 0.f;
    float m0 = -1e30f, m1 = -1e30f, l0 = 0.f, l1 = 0.f;

    const int row0 = q0 + w * 16 + g;
    const int row1 = row0 + 8;
    const int nkt = 2 * qt + 2;

    for (int kt = 0; kt < nkt; kt++) {
        const uint32_t buf = sb + BUF_OFF + (uint32_t)(kt & 1) * KVBUF;
        if (kt + 1 < nkt) {
            attn_load_kv(sb + BUF_OFF + (uint32_t)((kt + 1) & 1) * KVBUF,
                         kh, kl, vh, vl, (kt + 1) * 64, kvh, t);
            asm volatile("cp.async.commit_group;\n");
            asm volatile("cp.async.wait_group 1;\n");
        } else {
            asm volatile("cp.async.wait_group 0;\n");
        }
        __syncthreads();

        float sacc[8][4];
        #pragma unroll
        for (int j = 0; j < 8; j++)
            #pragma unroll
            for (int r = 0; r < 4; r++) sacc[j][r] = 0.f;

        #pragma unroll
        for (int kg = 0; kg < 4; kg++) {
            #pragma unroll
            for (int kc = 0; kc < 4; kc++) {
                uint32_t off = (uint32_t)((kg * 16 + (g8 & 1) * 8 + l8) * 144 +
                                          (kc * 16 + (g8 >> 1) * 8) * 2);
                uint32_t kbh[4], kbl[4];
                ldsm_x4(kbh, buf + off);
                ldsm_x4(kbl, buf + 9216 + off);
                uint32_t b0h[2] = {kbh[0], kbh[2]}, b1h[2] = {kbh[1], kbh[3]};
                uint32_t b0l[2] = {kbl[0], kbl[2]}, b1l[2] = {kbl[1], kbl[3]};
                mma16816(sacc[2 * kg],     qah[kc], b0h);
                mma16816(sacc[2 * kg],     qah[kc], b0l);
                mma16816(sacc[2 * kg],     qal[kc], b0h);
                mma16816(sacc[2 * kg + 1], qah[kc], b1h);
                mma16816(sacc[2 * kg + 1], qah[kc], b1l);
                mma16816(sacc[2 * kg + 1], qal[kc], b1h);
            }
        }

        if (kt >= 2 * qt) {
            #pragma unroll
            for (int j = 0; j < 8; j++) {
                int col = kt * 64 + j * 8 + tig * 2;
                if (col > row0)     sacc[j][0] = -1e30f;
                if (col + 1 > row0) sacc[j][1] = -1e30f;
                if (col > row1)     sacc[j][2] = -1e30f;
                if (col + 1 > row1) sacc[j][3] = -1e30f;
            }
        }

        float mx0 = -1e30f, mx1 = -1e30f;
        #pragma unroll
        for (int j = 0; j < 8; j++) {
            mx0 = fmaxf(mx0, fmaxf(sacc[j][0], sacc[j][1]));
            mx1 = fmaxf(mx1, fmaxf(sacc[j][2], sacc[j][3]));
        }
        mx0 = fmaxf(mx0, __shfl_xor_sync(0xffffffffu, mx0, 1));
        mx0 = fmaxf(mx0, __shfl_xor_sync(0xffffffffu, mx0, 2));
        mx1 = fmaxf(mx1, __shfl_xor_sync(0xffffffffu, mx1, 1));
        mx1 = fmaxf(mx1, __shfl_xor_sync(0xffffffffu, mx1, 2));

        float nm0 = fmaxf(m0, mx0), nm1 = fmaxf(m1, mx1);
        float al0 = __expf(m0 - nm0), al1 = __expf(m1 - nm1);
        m0 = nm0; m1 = nm1;

        float rs0 = 0.f, rs1 = 0.f;
        #pragma unroll
        for (int j = 0; j < 8; j++) {
            sacc[j][0] = __expf(sacc[j][0] - nm0);
            sacc[j][1] = __expf(sacc[j][1] - nm0);
            sacc[j][2] = __expf(sacc[j][2] - nm1);
            sacc[j][3] = __expf(sacc[j][3] - nm1);
            rs0 += sacc[j][0] + sacc[j][1];
            rs1 += sacc[j][2] + sacc[j][3];
        }
        rs0 += __shfl_xor_sync(0xffffffffu, rs0, 1);
        rs0 += __shfl_xor_sync(0xffffffffu, rs0, 2);
        rs1 += __shfl_xor_sync(0xffffffffu, rs1, 1);
        rs1 += __shfl_xor_sync(0xffffffffu, rs1, 2);
        l0 = l0 * al0 + rs0;
        l1 = l1 * al1 + rs1;
        #pragma unroll
        for (int j = 0; j < 8; j++) {
            oacc[j][0] *= al0; oacc[j][1] *= al0;
            oacc[j][2] *= al1; oacc[j][3] *= al1;
        }

        uint32_t pah[4][4], pal[4][4];
        #pragma unroll
        for (int kc = 0; kc < 4; kc++) {
            int j0 = 2 * kc, j1 = 2 * kc + 1;
            float p00 = sacc[j0][0], p01 = sacc[j0][1];
            float p02 = sacc[j0][2], p03 = sacc[j0][3];
            float p10 = sacc[j1][0], p11 = sacc[j1][1];
            float p12 = sacc[j1][2], p13 = sacc[j1][3];
            float h00 = __bfloat162float(__float2bfloat16(p00));
            float h01 = __bfloat162float(__float2bfloat16(p01));
            float h02 = __bfloat162float(__float2bfloat16(p02));
            float h03 = __bfloat162float(__float2bfloat16(p03));
            float h10 = __bfloat162float(__float2bfloat16(p10));
            float h11 = __bfloat162float(__float2bfloat16(p11));
            float h12 = __bfloat162float(__float2bfloat16(p12));
            float h13 = __bfloat162float(__float2bfloat16(p13));
            pah[kc][0] = packbf2(h00, h01);
            pah[kc][1] = packbf2(h02, h03);
            pah[kc][2] = packbf2(h10, h11);
            pah[kc][3] = packbf2(h12, h13);
            pal[kc][0] = packbf2(p00 - h00, p01 - h01);
            pal[kc][1] = packbf2(p02 - h02, p03 - h03);
            pal[kc][2] = packbf2(p10 - h10, p11 - h11);
            pal[kc][3] = packbf2(p12 - h12, p13 - h13);
        }

        #pragma unroll
        for (int kc = 0; kc < 4; kc++) {
            #pragma unroll
            for (int jj = 0; jj < 4; jj++) {
                uint32_t off = (uint32_t)((kc * 16 + (g8 & 1) * 8 + l8) * 144 +
                                          (jj * 16 + (g8 >> 1) * 8) * 2);
                uint32_t vbh[4], vbl[4];
                ldsm_x4_t(vbh, buf + 18432 + off);
                ldsm_x4_t(vbl, buf + 27648 + off);
                uint32_t b0h[2] = {vbh[0], vbh[1]}, b1h[2] = {vbh[2], vbh[3]};
                uint32_t b0l[2] = {vbl[0], vbl[1]}, b1l[2] = {vbl[2], vbl[3]};
                mma16816(oacc[2 * jj],     pah[kc], b0h);
                mma16816(oacc[2 * jj],     pah[kc], b0l);
                mma16816(oacc[2 * jj],     pal[kc], b0h);
                mma16816(oacc[2 * jj + 1], pah[kc], b1h);
                mma16816(oacc[2 * jj + 1], pah[kc], b1l);
                mma16816(oacc[2 * jj + 1], pal[kc], b1h);
            }
        }
        __syncthreads();
    }

    float i0 = 1.0f / l0, i1 = 1.0f / l1;
    #pragma unroll
    for (int j = 0; j < 8; j++) {
        int col = h * HD + j * 8 + tig * 2;
        float o0 = oacc[j][0] * i0, o1 = oacc[j][1] * i0;
        float o2 = oacc[j][2] * i1, o3 = oacc[j][3] * i1;
        float h0 = __bfloat162float(__float2bfloat16(o0));
        float h1 = __bfloat162float(__float2bfloat16(o1));
        float h2 = __bfloat162float(__float2bfloat16(o2));
        float h3 = __bfloat162float(__float2bfloat16(o3));
        *(uint32_t*)&Oh[(size_t)row0 * HID + col] = packbf2(h0, h1);
        *(uint32_t*)&Oh[(size_t)row1 * HID + col] = packbf2(h2, h3);
        *(uint32_t*)&Ol[(size_t)row0 * HID + col] = packbf2(o0 - h0, o1 - h1);
        *(uint32_t*)&Ol[(size_t)row1 * HID + col] = packbf2(o2 - h2, o3 - h3);
    }
}

// ---------------- launch ----------------
extern "C" void kernel_launch(void* const* d_in, const int* in_sizes, int n_in,
                              void* d_out, int out_size)
{
    const float* X   = (const float*)d_in[0];
    const int*   pid = (const int*)d_in[2];
    const float* Wq  = (const float*)d_in[3];
    const float* Wk  = (const float*)d_in[4];
    const float* Wv  = (const float*)d_in[5];
    const float* Wo  = (const float*)d_in[6];
    float* out = (float*)d_out;

    float *q, *kv;
    cudaGetSymbolAddress((void**)&q,  g_q);
    cudaGetSymbolAddress((void**)&kv, g_kv);
    __nv_bfloat16 *Xh, *Xl, *Wqh, *Wql, *Wkvh, *Wkvl, *Woh, *Wol, *Ah, *Al;
    __nv_bfloat16 *qh, *ql, *kh, *kl, *vh, *vl;
    cudaGetSymbolAddress((void**)&Xh,  g_Xhi);   cudaGetSymbolAddress((void**)&Xl,  g_Xlo);
    cudaGetSymbolAddress((void**)&Wqh, g_Wqhi);  cudaGetSymbolAddress((void**)&Wql, g_Wqlo);
    cudaGetSymbolAddress((void**)&Wkvh,g_Wkvhi); cudaGetSymbolAddress((void**)&Wkvl,g_Wkvlo);
    cudaGetSymbolAddress((void**)&Woh, g_Wohi);  cudaGetSymbolAddress((void**)&Wol, g_Wolo);
    cudaGetSymbolAddress((void**)&Ah,  g_Ahi);   cudaGetSymbolAddress((void**)&Al,  g_Alo);
    cudaGetSymbolAddress((void**)&qh,  g_qh);    cudaGetSymbolAddress((void**)&ql,  g_ql);
    cudaGetSymbolAddress((void**)&kh,  g_kh);    cudaGetSymbolAddress((void**)&kl,  g_kl);
    cudaGetSymbolAddress((void**)&vh,  g_vh);    cudaGetSymbolAddress((void**)&vl,  g_vl);

    cudaFuncSetAttribute(mma_gemm, cudaFuncAttributeMaxDynamicSharedMemorySize,
                         GEMM_SMEM_BYTES);
    cudaFuncSetAttribute(attn_tc, cudaFuncAttributeMaxDynamicSharedMemorySize,
                         ATTN_SMEM);

    // order chosen so a GEMM lands in the ncu-profiled slot
    split_k<<<(S_LEN * HID) / 256, 256>>>(X,  Xh,  Xl,  S_LEN * HID);
    split_k<<<(HID * HID) / 256, 256>>>(Wq, Wqh, Wql, HID * HID);
    mma_gemm<<<dim3(HID / BN, S_LEN / BM), 256, GEMM_SMEM_BYTES>>>(
        Xh, Xl, Wqh, Wql, q, S_LEN, HID, HID);
    split_pack_k<<<(HID * 512) / 256, 256>>>(Wk, Wkvh, Wkvl, HID, 512, KVW, 0);
    split_pack_k<<<(HID * 512) / 256, 256>>>(Wv, Wkvh, Wkvl, HID, 512, KVW, 512);
    mma_gemm<<<dim3(KVW / BN, S_LEN / BM), 256, GEMM_SMEM_BYTES>>>(
        Xh, Xl, Wkvh, Wkvl, kv, S_LEN, KVW, HID);
    split_k<<<(HID * HID) / 256, 256>>>(Wo, Woh, Wol, HID * HID);

    {
        int total = S_LEN * 48 * 32;
        rope_split_k<<<(total + 255) / 256, 256>>>(q, kv, pid, qh, ql, kh, kl, vh, vl);
    }

    attn_tc<<<dim3(16, NH), 256, ATTN_SMEM>>>(qh, ql, kh, kl, vh, vl, Ah, Al);

    mma_gemm<<<dim3(HID / BN, S_LEN / BM), 256, GEMM_SMEM_BYTES>>>(
        Ah, Al, Woh, Wol, out, S_LEN, HID, HID);
}

// round 6
// speedup vs baseline: 1.0537x; 1.0537x over previous
#include <cuda_runtime.h>
#include <cuda_bf16.h>
#include <math.h>
#include <stdint.h>

#define S_LEN 2048
#define HID   2048
#define NH    32
#define NKV   8
#define HD    64
#define KVW   1024          // combined [K|V] width
#define NQKV  3072          // fused Q|K|V projection width

// ---------------- scratch (no allocs allowed) ----------------
__device__ float g_q [S_LEN * HID];
__device__ float g_kv[S_LEN * KVW];   // cols 0..511 = K, 512..1023 = V

__device__ __nv_bfloat16 g_Xhi [S_LEN * HID],  g_Xlo [S_LEN * HID];
__device__ __nv_bfloat16 g_Wqkvh[HID * NQKV],  g_Wqkvl[HID * NQKV];
__device__ __nv_bfloat16 g_Wohi[HID * HID],    g_Wolo[HID * HID];
__device__ __nv_bfloat16 g_Ahi [S_LEN * HID],  g_Alo [S_LEN * HID];

// attention operands (bf16 hi/lo after RoPE)
__device__ __nv_bfloat16 g_qh[S_LEN * HID], g_ql[S_LEN * HID];
__device__ __nv_bfloat16 g_kh[S_LEN * 512], g_kl[S_LEN * 512];
__device__ __nv_bfloat16 g_vh[S_LEN * 512], g_vl[S_LEN * 512];

// ---------------- helpers ----------------
__device__ __forceinline__ uint32_t sptr(const void* p) {
    return (uint32_t)__cvta_generic_to_shared(p);
}
__device__ __forceinline__ void cp16(uint32_t dst, const void* src) {
    asm volatile("cp.async.cg.shared.global [%0], [%1], 16;\n" :: "r"(dst), "l"(src));
}
__device__ __forceinline__ void ldsm_x4(uint32_t* r, uint32_t addr) {
    asm volatile("ldmatrix.sync.aligned.m8n8.x4.shared.b16 {%0,%1,%2,%3}, [%4];\n"
        : "=r"(r[0]), "=r"(r[1]), "=r"(r[2]), "=r"(r[3]) : "r"(addr));
}
__device__ __forceinline__ void ldsm_x4_t(uint32_t* r, uint32_t addr) {
    asm volatile("ldmatrix.sync.aligned.m8n8.x4.trans.shared.b16 {%0,%1,%2,%3}, [%4];\n"
        : "=r"(r[0]), "=r"(r[1]), "=r"(r[2]), "=r"(r[3]) : "r"(addr));
}
__device__ __forceinline__ void mma16816(float* c, const uint32_t* a, const uint32_t* b) {
    asm volatile(
        "mma.sync.aligned.m16n8k16.row.col.f32.bf16.bf16.f32 "
        "{%0,%1,%2,%3}, {%4,%5,%6,%7}, {%8,%9}, {%0,%1,%2,%3};\n"
        : "+f"(c[0]), "+f"(c[1]), "+f"(c[2]), "+f"(c[3])
        : "r"(a[0]), "r"(a[1]), "r"(a[2]), "r"(a[3]), "r"(b[0]), "r"(b[1]));
}
__device__ __forceinline__ uint32_t packbf2(float x, float y) {
    __nv_bfloat162 h = __floats2bfloat162_rn(x, y);
    return *(uint32_t*)&h;
}

// ---------------- splits ----------------
__global__ void split_k(const float* __restrict__ in,
                        __nv_bfloat16* __restrict__ hi,
                        __nv_bfloat16* __restrict__ lo, int n)
{
    int i = blockIdx.x * 256 + threadIdx.x;
    if (i >= n) return;
    float x = in[i];
    __nv_bfloat16 h = __float2bfloat16(x);
    hi[i] = h;
    lo[i] = __float2bfloat16(x - __bfloat162float(h));
}

__global__ void split_pack_k(const float* __restrict__ in,
                             __nv_bfloat16* __restrict__ hi,
                             __nv_bfloat16* __restrict__ lo,
                             int rows, int cols, int ostride, int ooff)
{
    int i = blockIdx.x * 256 + threadIdx.x;
    if (i >= rows * cols) return;
    int r = i / cols, c = i % cols;
    float x = in[i];
    __nv_bfloat16 h = __float2bfloat16(x);
    int o = r * ostride + ooff + c;
    hi[o] = h;
    lo[o] = __float2bfloat16(x - __bfloat162float(h));
}

// ---------------- tensor-core GEMM: 128x128 CTA, 4 warps, 64x64 warp tile ----------------
// 2 CTAs/SM, 2-stage cp.async, bf16x3 split. Output split across (C0|C1) at Nsplit.
#define BM 128
#define BN 128
#define BK 32
#define ASTRIDE 40                       // elems; 80B rows
#define BSTRIDE 136                      // elems; 272B rows
#define A_T (BM * ASTRIDE)               // 5120 elems
#define B_T (BK * BSTRIDE)               // 4352 elems
#define STAGE_ELEMS (2 * A_T + 2 * B_T)  // 18944 elems
#define GEMM_SMEM_BYTES (2 * STAGE_ELEMS * 2)   // 75776 bytes

__device__ __forceinline__ void load_tile(
    __nv_bfloat16* sm,
    const __nv_bfloat16* __restrict__ Ah, const __nv_bfloat16* __restrict__ Al,
    const __nv_bfloat16* __restrict__ Bh, const __nv_bfloat16* __restrict__ Bl,
    int K, int NB, int m0, int n0, int k0, int t)
{
    // A tile: 128 rows x 32 cols = 512 16B chunks (hi and lo)
    #pragma unroll
    for (int c = t; c < 512; c += 128) {
        int row = c >> 2, col = (c & 3) * 8;
        size_t g = (size_t)(m0 + row) * K + k0 + col;
        uint32_t s = (uint32_t)(row * ASTRIDE + col);
        cp16(sptr(sm + s),       Ah + g);
        cp16(sptr(sm + A_T + s), Al + g);
    }
    // B tile: 32 rows x 128 cols = 512 16B chunks (hi and lo)
    #pragma unroll
    for (int c = t; c < 512; c += 128) {
        int row = c >> 4, col = (c & 15) * 8;
        size_t g = (size_t)(k0 + row) * NB + n0 + col;
        uint32_t s = (uint32_t)(row * BSTRIDE + col);
        cp16(sptr(sm + 2 * A_T + s),       Bh + g);
        cp16(sptr(sm + 2 * A_T + B_T + s), Bl + g);
    }
}

__global__ __launch_bounds__(128, 2) void mma_gemm(
    const __nv_bfloat16* __restrict__ Ah, const __nv_bfloat16* __restrict__ Al,
    const __nv_bfloat16* __restrict__ Bh, const __nv_bfloat16* __restrict__ Bl,
    float* __restrict__ C0, float* __restrict__ C1,
    int Nsplit, int ld0, int ld1, int NB, int K)
{
    extern __shared__ __nv_bfloat16 sm[];
    const int t = threadIdx.x, lane = t & 31, w = t >> 5;
    const int wm = w >> 1, wn = w & 1;            // 2x2 warps, 64x64 warp tile
    const int m0 = blockIdx.y * BM, n0 = blockIdx.x * BN;

    float acc[4][8][4];
    #pragma unroll
    for (int i = 0; i < 4; i++)
        #pragma unroll
        for (int j = 0; j < 8; j++)
            #pragma unroll
            for (int r = 0; r < 4; r++) acc[i][j][r] = 0.f;

    const int g8 = lane >> 3;
    const int l8 = lane & 7;

    load_tile(sm, Ah, Al, Bh, Bl, K, NB, m0, n0, 0, t);
    asm volatile("cp.async.commit_group;\n");

    const int nk = K / BK;
    for (int kt = 0; kt < nk; kt++) {
        __nv_bfloat16* buf = sm + (kt & 1) * STAGE_ELEMS;
        if (kt + 1 < nk) {
            load_tile(sm + ((kt + 1) & 1) * STAGE_ELEMS, Ah, Al, Bh, Bl,
                      K, NB, m0, n0, (kt + 1) * BK, t);
            asm volatile("cp.async.commit_group;\n");
            asm volatile("cp.async.wait_group 1;\n");
        } else {
            asm volatile("cp.async.wait_group 0;\n");
        }
        __syncthreads();

        #pragma unroll
        for (int ks = 0; ks < 2; ks++) {
            uint32_t ah[4][4], al[4][4], bh[8][2], bl[8][2];
            #pragma unroll
            for (int i = 0; i < 4; i++) {
                int row = wm * 64 + i * 16 + (g8 & 1) * 8 + l8;
                int col = ks * 16 + (g8 >> 1) * 8;
                ldsm_x4(ah[i], sptr(buf + row * ASTRIDE + col));
                ldsm_x4(al[i], sptr(buf + A_T + row * ASTRIDE + col));
            }
            #pragma unroll
            for (int jj = 0; jj < 4; jj++) {
                int krow = ks * 16 + (g8 & 1) * 8 + l8;
                int ncol = wn * 64 + jj * 16 + (g8 >> 1) * 8;
                uint32_t r4[4];
                ldsm_x4_t(r4, sptr(buf + 2 * A_T + krow * BSTRIDE + ncol));
                bh[2 * jj][0] = r4[0]; bh[2 * jj][1] = r4[1];
                bh[2 * jj + 1][0] = r4[2]; bh[2 * jj + 1][1] = r4[3];
                ldsm_x4_t(r4, sptr(buf + 2 * A_T + B_T + krow * BSTRIDE + ncol));
                bl[2 * jj][0] = r4[0]; bl[2 * jj][1] = r4[1];
                bl[2 * jj + 1][0] = r4[2]; bl[2 * jj + 1][1] = r4[3];
            }
            #pragma unroll
            for (int i = 0; i < 4; i++)
                #pragma unroll
                for (int j = 0; j < 8; j++) {
                    mma16816(acc[i][j], ah[i], bh[j]);
                    mma16816(acc[i][j], ah[i], bl[j]);
                    mma16816(acc[i][j], al[i], bh[j]);
                }
        }
        __syncthreads();
    }

    // epilogue: whole CTA sits on one side of Nsplit (BN divides Nsplit)
    float* Cp; int ldc, nb;
    if (n0 < Nsplit) { Cp = C0; ldc = ld0; nb = n0; }
    else             { Cp = C1; ldc = ld1; nb = n0 - Nsplit; }
    #pragma unroll
    for (int i = 0; i < 4; i++)
        #pragma unroll
        for (int j = 0; j < 8; j++) {
            int row = m0 + wm * 64 + i * 16 + (lane >> 2);
            int col = nb + wn * 64 + j * 8 + (lane & 3) * 2;
            *(float2*)&Cp[(size_t)row * ldc + col] =
                make_float2(acc[i][j][0], acc[i][j][1]);
            *(float2*)&Cp[(size_t)(row + 8) * ldc + col] =
                make_float2(acc[i][j][2], acc[i][j][3]);
        }
}

// ---------------- fused RoPE + bf16 hi/lo split ----------------
__global__ void rope_split_k(const float* __restrict__ q,
                             const float* __restrict__ kv,
                             const int* __restrict__ pos_ids,
                             __nv_bfloat16* __restrict__ qh, __nv_bfloat16* __restrict__ ql,
                             __nv_bfloat16* __restrict__ kh, __nv_bfloat16* __restrict__ kl,
                             __nv_bfloat16* __restrict__ vh, __nv_bfloat16* __restrict__ vl)
{
    int idx = blockIdx.x * blockDim.x + threadIdx.x;
    const int total = S_LEN * 48 * 32;
    if (idx >= total) return;

    int d    = idx & 31;
    int rest = idx >> 5;
    int hh   = rest % 48;
    int s    = rest / 48;

    if (hh < 40) {
        float pos = (float)pos_ids[s];
        float inv = __powf(10000.0f, -(float)d * (1.0f / 32.0f));
        float ang = pos * inv;
        float c, sn;
        __sincosf(ang, &sn, &c);
        if (hh < 32) {
            const float* p = q + (size_t)s * HID + hh * HD;
            float x1 = p[d], x2 = p[d + 32];
            size_t o1 = (size_t)s * HID + hh * HD + d, o2 = o1 + 32;
            float y1 = (x1 * c - x2 * sn) * 0.125f;
            float y2 = (x2 * c + x1 * sn) * 0.125f;
            __nv_bfloat16 h1 = __float2bfloat16(y1), h2 = __float2bfloat16(y2);
            qh[o1] = h1; ql[o1] = __float2bfloat16(y1 - __bfloat162float(h1));
            qh[o2] = h2; ql[o2] = __float2bfloat16(y2 - __bfloat162float(h2));
        } else {
            const float* p = kv + (size_t)s * KVW + (hh - 32) * HD;
            float x1 = p[d], x2 = p[d + 32];
            size_t o1 = (size_t)s * 512 + (hh - 32) * HD + d, o2 = o1 + 32;
            float y1 = x1 * c - x2 * sn;
            float y2 = x2 * c + x1 * sn;
            __nv_bfloat16 h1 = __float2bfloat16(y1), h2 = __float2bfloat16(y2);
            kh[o1] = h1; kl[o1] = __float2bfloat16(y1 - __bfloat162float(h1));
            kh[o2] = h2; kl[o2] = __float2bfloat16(y2 - __bfloat162float(h2));
        }
    } else {
        const float* p = kv + (size_t)s * KVW + 512 + (hh - 40) * HD;
        float x1 = p[d], x2 = p[d + 32];
        size_t o1 = (size_t)s * 512 + (hh - 40) * HD + d, o2 = o1 + 32;
        __nv_bfloat16 h1 = __float2bfloat16(x1), h2 = __float2bfloat16(x2);
        vh[o1] = h1; vl[o1] = __float2bfloat16(x1 - __bfloat162float(h1));
        vh[o2] = h2; vl[o2] = __float2bfloat16(x2 - __bfloat162float(h2));
    }
}

// ---------------- tensor-core flash attention (causal) ----------------
#define QHI_OFF 0
#define QLO_OFF (128 * 144)
#define BUF_OFF (2 * 128 * 144)
#define KVBUF   (4 * 64 * 144)
#define ATTN_SMEM (BUF_OFF + 2 * KVBUF)

__device__ __forceinline__ void attn_load_kv(
    uint32_t bufb,
    const __nv_bfloat16* __restrict__ kh, const __nv_bfloat16* __restrict__ kl,
    const __nv_bfloat16* __restrict__ vh, const __nv_bfloat16* __restrict__ vl,
    int k0, int kvh, int t)
{
    #pragma unroll
    for (int i = 0; i < 2; i++) {
        int idx = i * 256 + t;
        int row = idx >> 3, cc = idx & 7;
        uint32_t off = (uint32_t)(row * 144 + cc * 16);
        size_t g = (size_t)(k0 + row) * 512 + kvh * HD + cc * 8;
        cp16(bufb + off,         kh + g);
        cp16(bufb + 9216 + off,  kl + g);
        cp16(bufb + 18432 + off, vh + g);
        cp16(bufb + 27648 + off, vl + g);
    }
}

__global__ __launch_bounds__(256) void attn_tc(
    const __nv_bfloat16* __restrict__ qh, const __nv_bfloat16* __restrict__ ql,
    const __nv_bfloat16* __restrict__ kh, const __nv_bfloat16* __restrict__ kl,
    const __nv_bfloat16* __restrict__ vh, const __nv_bfloat16* __restrict__ vl,
    __nv_bfloat16* __restrict__ Oh, __nv_bfloat16* __restrict__ Ol)
{
    extern __shared__ __align__(1024) char asmem[];
    const uint32_t sb = sptr(asmem);
    const int qt  = 15 - blockIdx.x;
    const int h   = blockIdx.y;
    const int kvh = h >> 2;
    const int t = threadIdx.x, w = t >> 5, lane = t & 31;
    const int g8 = lane >> 3, l8 = lane & 7, tig = lane & 3, g = lane >> 2;
    const int q0 = qt * 128;

    #pragma unroll
    for (int i = 0; i < 4; i++) {
        int idx = i * 256 + t;
        int row = idx >> 3, cc = idx & 7;
        uint32_t off = (uint32_t)(row * 144 + cc * 16);
        size_t gg = (size_t)(q0 + row) * HID + h * HD + cc * 8;
        cp16(sb + QHI_OFF + off, qh + gg);
        cp16(sb + QLO_OFF + off, ql + gg);
    }
    attn_load_kv(sb + BUF_OFF, kh, kl, vh, vl, 0, kvh, t);
    asm volatile("cp.async.commit_group;\n");
    asm volatile("cp.async.wait_group 0;\n");
    __syncthreads();

    uint32_t qah[4][4], qal[4][4];
    #pragma unroll
    for (int kc = 0; kc < 4; kc++) {
        uint32_t off = (uint32_t)((w * 16 + (g8 & 1) * 8 + l8) * 144 +
                                  (kc * 16 + (g8 >> 1) * 8) * 2);
        ldsm_x4(qah[kc], sb + QHI_OFF + off);
        ldsm_x4(qal[kc], sb + QLO_OFF + off);
    }

    float oacc[8][4];
    #pragma unroll
    for (int j = 0; j < 8; j++)
        #pragma unroll
        for (int r = 0; r < 4; r++) oacc[j][r] = 0.f;
    float m0 = -1e30f, m1 = -1e30f, l0 = 0.f, l1 = 0.f;

    const int row0 = q0 + w * 16 + g;
    const int row1 = row0 + 8;
    const int nkt = 2 * qt + 2;

    for (int kt = 0; kt < nkt; kt++) {
        const uint32_t buf = sb + BUF_OFF + (uint32_t)(kt & 1) * KVBUF;
        if (kt + 1 < nkt) {
            attn_load_kv(sb + BUF_OFF + (uint32_t)((kt + 1) & 1) * KVBUF,
                         kh, kl, vh, vl, (kt + 1) * 64, kvh, t);
            asm volatile("cp.async.commit_group;\n");
            asm volatile("cp.async.wait_group 1;\n");
        } else {
            asm volatile("cp.async.wait_group 0;\n");
        }
        __syncthreads();

        float sacc[8][4];
        #pragma unroll
        for (int j = 0; j < 8; j++)
            #pragma unroll
            for (int r = 0; r < 4; r++) sacc[j][r] = 0.f;

        #pragma unroll
        for (int kg = 0; kg < 4; kg++) {
            #pragma unroll
            for (int kc = 0; kc < 4; kc++) {
                uint32_t off = (uint32_t)((kg * 16 + (g8 & 1) * 8 + l8) * 144 +
                                          (kc * 16 + (g8 >> 1) * 8) * 2);
                uint32_t kbh[4], kbl[4];
                ldsm_x4(kbh, buf + off);
                ldsm_x4(kbl, buf + 9216 + off);
                uint32_t b0h[2] = {kbh[0], kbh[2]}, b1h[2] = {kbh[1], kbh[3]};
                uint32_t b0l[2] = {kbl[0], kbl[2]}, b1l[2] = {kbl[1], kbl[3]};
                mma16816(sacc[2 * kg],     qah[kc], b0h);
                mma16816(sacc[2 * kg],     qah[kc], b0l);
                mma16816(sacc[2 * kg],     qal[kc], b0h);
                mma16816(sacc[2 * kg + 1], qah[kc], b1h);
                mma16816(sacc[2 * kg + 1], qah[kc], b1l);
                mma16816(sacc[2 * kg + 1], qal[kc], b1h);
            }
        }

        if (kt >= 2 * qt) {
            #pragma unroll
            for (int j = 0; j < 8; j++) {
                int col = kt * 64 + j * 8 + tig * 2;
                if (col > row0)     sacc[j][0] = -1e30f;
                if (col + 1 > row0) sacc[j][1] = -1e30f;
                if (col > row1)     sacc[j][2] = -1e30f;
                if (col + 1 > row1) sacc[j][3] = -1e30f;
            }
        }

        float mx0 = -1e30f, mx1 = -1e30f;
        #pragma unroll
        for (int j = 0; j < 8; j++) {
            mx0 = fmaxf(mx0, fmaxf(sacc[j][0], sacc[j][1]));
            mx1 = fmaxf(mx1, fmaxf(sacc[j][2], sacc[j][3]));
        }
        mx0 = fmaxf(mx0, __shfl_xor_sync(0xffffffffu, mx0, 1));
        mx0 = fmaxf(mx0, __shfl_xor_sync(0xffffffffu, mx0, 2));
        mx1 = fmaxf(mx1, __shfl_xor_sync(0xffffffffu, mx1, 1));
        mx1 = fmaxf(mx1, __shfl_xor_sync(0xffffffffu, mx1, 2));

        float nm0 = fmaxf(m0, mx0), nm1 = fmaxf(m1, mx1);
        float al0 = __expf(m0 - nm0), al1 = __expf(m1 - nm1);
        m0 = nm0; m1 = nm1;

        float rs0 = 0.f, rs1 = 0.f;
        #pragma unroll
        for (int j = 0; j < 8; j++) {
            sacc[j][0] = __expf(sacc[j][0] - nm0);
            sacc[j][1] = __expf(sacc[j][1] - nm0);
            sacc[j][2] = __expf(sacc[j][2] - nm1);
            sacc[j][3] = __expf(sacc[j][3] - nm1);
            rs0 += sacc[j][0] + sacc[j][1];
            rs1 += sacc[j][2] + sacc[j][3];
        }
        rs0 += __shfl_xor_sync(0xffffffffu, rs0, 1);
        rs0 += __shfl_xor_sync(0xffffffffu, rs0, 2);
        rs1 += __shfl_xor_sync(0xffffffffu, rs1, 1);
        rs1 += __shfl_xor_sync(0xffffffffu, rs1, 2);
        l0 = l0 * al0 + rs0;
        l1 = l1 * al1 + rs1;
        #pragma unroll
        for (int j = 0; j < 8; j++) {
            oacc[j][0] *= al0; oacc[j][1] *= al0;
            oacc[j][2] *= al1; oacc[j][3] *= al1;
        }

        uint32_t pah[4][4], pal[4][4];
        #pragma unroll
        for (int kc = 0; kc < 4; kc++) {
            int j0 = 2 * kc, j1 = 2 * kc + 1;
            float p00 = sacc[j0][0], p01 = sacc[j0][1];
            float p02 = sacc[j0][2], p03 = sacc[j0][3];
            float p10 = sacc[j1][0], p11 = sacc[j1][1];
            float p12 = sacc[j1][2], p13 = sacc[j1][3];
            float h00 = __bfloat162float(__float2bfloat16(p00));
            float h01 = __bfloat162float(__float2bfloat16(p01));
            float h02 = __bfloat162float(__float2bfloat16(p02));
            float h03 = __bfloat162float(__float2bfloat16(p03));
            float h10 = __bfloat162float(__float2bfloat16(p10));
            float h11 = __bfloat162float(__float2bfloat16(p11));
            float h12 = __bfloat162float(__float2bfloat16(p12));
            float h13 = __bfloat162float(__float2bfloat16(p13));
            pah[kc][0] = packbf2(h00, h01);
            pah[kc][1] = packbf2(h02, h03);
            pah[kc][2] = packbf2(h10, h11);
            pah[kc][3] = packbf2(h12, h13);
            pal[kc][0] = packbf2(p00 - h00, p01 - h01);
            pal[kc][1] = packbf2(p02 - h02, p03 - h03);
            pal[kc][2] = packbf2(p10 - h10, p11 - h11);
            pal[kc][3] = packbf2(p12 - h12, p13 - h13);
        }

        #pragma unroll
        for (int kc = 0; kc < 4; kc++) {
            #pragma unroll
            for (int jj = 0; jj < 4; jj++) {
                uint32_t off = (uint32_t)((kc * 16 + (g8 & 1) * 8 + l8) * 144 +
                                          (jj * 16 + (g8 >> 1) * 8) * 2);
                uint32_t vbh[4], vbl[4];
                ldsm_x4_t(vbh, buf + 18432 + off);
                ldsm_x4_t(vbl, buf + 27648 + off);
                uint32_t b0h[2] = {vbh[0], vbh[1]}, b1h[2] = {vbh[2], vbh[3]};
                uint32_t b0l[2] = {vbl[0], vbl[1]}, b1l[2] = {vbl[2], vbl[3]};
                mma16816(oacc[2 * jj],     pah[kc], b0h);
                mma16816(oacc[2 * jj],     pah[kc], b0l);
                mma16816(oacc[2 * jj],     pal[kc], b0h);
                mma16816(oacc[2 * jj + 1], pah[kc], b1h);
                mma16816(oacc[2 * jj + 1], pah[kc], b1l);
                mma16816(oacc[2 * jj + 1], pal[kc], b1h);
            }
        }
        __syncthreads();
    }

    float i0 = 1.0f / l0, i1 = 1.0f / l1;
    #pragma unroll
    for (int j = 0; j < 8; j++) {
        int col = h * HD + j * 8 + tig * 2;
        float o0 = oacc[j][0] * i0, o1 = oacc[j][1] * i0;
        float o2 = oacc[j][2] * i1, o3 = oacc[j][3] * i1;
        float h0 = __bfloat162float(__float2bfloat16(o0));
        float h1 = __bfloat162float(__float2bfloat16(o1));
        float h2 = __bfloat162float(__float2bfloat16(o2));
        float h3 = __bfloat162float(__float2bfloat16(o3));
        *(uint32_t*)&Oh[(size_t)row0 * HID + col] = packbf2(h0, h1);
        *(uint32_t*)&Oh[(size_t)row1 * HID + col] = packbf2(h2, h3);
        *(uint32_t*)&Ol[(size_t)row0 * HID + col] = packbf2(o0 - h0, o1 - h1);
        *(uint32_t*)&Ol[(size_t)row1 * HID + col] = packbf2(o2 - h2, o3 - h3);
    }
}

// ---------------- launch ----------------
extern "C" void kernel_launch(void* const* d_in, const int* in_sizes, int n_in,
                              void* d_out, int out_size)
{
    const float* X   = (const float*)d_in[0];
    const int*   pid = (const int*)d_in[2];
    const float* Wq  = (const float*)d_in[3];
    const float* Wk  = (const float*)d_in[4];
    const float* Wv  = (const float*)d_in[5];
    const float* Wo  = (const float*)d_in[6];
    float* out = (float*)d_out;

    float *q, *kv;
    cudaGetSymbolAddress((void**)&q,  g_q);
    cudaGetSymbolAddress((void**)&kv, g_kv);
    __nv_bfloat16 *Xh, *Xl, *Wqkvh, *Wqkvl, *Woh, *Wol, *Ah, *Al;
    __nv_bfloat16 *qh, *ql, *kh, *kl, *vh, *vl;
    cudaGetSymbolAddress((void**)&Xh,   g_Xhi);    cudaGetSymbolAddress((void**)&Xl,   g_Xlo);
    cudaGetSymbolAddress((void**)&Wqkvh,g_Wqkvh);  cudaGetSymbolAddress((void**)&Wqkvl,g_Wqkvl);
    cudaGetSymbolAddress((void**)&Woh,  g_Wohi);   cudaGetSymbolAddress((void**)&Wol,  g_Wolo);
    cudaGetSymbolAddress((void**)&Ah,   g_Ahi);    cudaGetSymbolAddress((void**)&Al,   g_Alo);
    cudaGetSymbolAddress((void**)&qh,   g_qh);     cudaGetSymbolAddress((void**)&ql,   g_ql);
    cudaGetSymbolAddress((void**)&kh,   g_kh);     cudaGetSymbolAddress((void**)&kl,   g_kl);
    cudaGetSymbolAddress((void**)&vh,   g_vh);     cudaGetSymbolAddress((void**)&vl,   g_vl);

    cudaFuncSetAttribute(mma_gemm, cudaFuncAttributeMaxDynamicSharedMemorySize,
                         GEMM_SMEM_BYTES);
    cudaFuncSetAttribute(attn_tc, cudaFuncAttributeMaxDynamicSharedMemorySize,
                         ATTN_SMEM);

    // splits (5 launches), then QKV GEMM as launch #5 (0-indexed) for ncu -s 5
    split_k<<<(S_LEN * HID) / 256, 256>>>(X, Xh, Xl, S_LEN * HID);
    split_pack_k<<<(HID * HID) / 256, 256>>>(Wq, Wqkvh, Wqkvl, HID, 2048, NQKV, 0);
    split_pack_k<<<(HID * 512) / 256, 256>>>(Wk, Wqkvh, Wqkvl, HID, 512, NQKV, 2048);
    split_pack_k<<<(HID * 512) / 256, 256>>>(Wv, Wqkvh, Wqkvl, HID, 512, NQKV, 2560);
    split_k<<<(HID * HID) / 256, 256>>>(Wo, Woh, Wol, HID * HID);

    // fused QKV projection: C cols [0,2048) -> q, [2048,3072) -> kv
    mma_gemm<<<dim3(NQKV / BN, S_LEN / BM), 128, GEMM_SMEM_BYTES>>>(
        Xh, Xl, Wqkvh, Wqkvl, q, kv, 2048, HID, KVW, NQKV, HID);

    {
        int total = S_LEN * 48 * 32;
        rope_split_k<<<(total + 255) / 256, 256>>>(q, kv, pid, qh, ql, kh, kl, vh, vl);
    }

    attn_tc<<<dim3(16, NH), 256, ATTN_SMEM>>>(qh, ql, kh, kl, vh, vl, Ah, Al);

    // output projection
    mma_gemm<<<dim3(HID / BN, S_LEN / BM), 128, GEMM_SMEM_BYTES>>>(
        Ah, Al, Woh, Wol, out, out, HID, HID, HID, HID, HID);
}